// round 1
// baseline (speedup 1.0000x reference)
#include <cuda_runtime.h>
#include <math.h>

#define SEQ   1024
#define DIM   1024
#define NHEAD 16
#define HD    64
#define FFD   4096
#define DEPTH 24
#define OUTD  2560

// ---------------- scratch (device globals; no allocations) ----------------
__device__ float g_x   [SEQ*DIM];
__device__ float g_h   [SEQ*DIM];      // ln output; also viewed as [256,4096]
__device__ float g_qkv [SEQ*3*DIM];
__device__ float g_qr  [NHEAD*SEQ*HD];
__device__ float g_kr  [NHEAD*SEQ*HD];
__device__ float g_vr  [NHEAD*SEQ*HD];
__device__ float g_attn[SEQ*DIM];
__device__ float g_ff  [SEQ*FFD];      // also merger hidden [256,4096]
__device__ float g_ds  [3*SEQ*DIM];
__device__ float g_cos [SEQ*HD];
__device__ float g_sin [SEQ*HD];

__device__ __forceinline__ float gelu_exact(float x) {
    return 0.5f * x * (1.0f + erff(x * 0.70710678118654752f));
}

// ---------------- generic SGEMM: C = op(A[M,K] @ B[N,K]^T + bias) ----------
// flags: bit0 = add residual Cres, bit1 = exact gelu
// All M % 128 == 0, N % 128 == 0, K % 8 == 0 in this model.
__global__ void __launch_bounds__(256) gemm_nt(
    const float* __restrict__ A, const float* __restrict__ B,
    const float* __restrict__ bias, const float* __restrict__ Cres,
    float* __restrict__ C, int M, int N, int K, int flags)
{
    __shared__ float As[8][128];
    __shared__ float Bs[8][128];
    const int bm = blockIdx.y * 128, bn = blockIdx.x * 128;
    const int tid = threadIdx.x;
    const int tx = tid & 15, ty = tid >> 4;
    const int lr = tid >> 1, lc = (tid & 1) * 4;

    const float* Ap = A + (size_t)(bm + lr) * K + lc;
    const float* Bp = B + (size_t)(bn + lr) * K + lc;

    float acc[8][8];
#pragma unroll
    for (int i = 0; i < 8; i++)
#pragma unroll
        for (int j = 0; j < 8; j++) acc[i][j] = 0.f;

    for (int k0 = 0; k0 < K; k0 += 8) {
        float4 av = *(const float4*)(Ap + k0);
        float4 bv = *(const float4*)(Bp + k0);
        As[lc + 0][lr] = av.x; As[lc + 1][lr] = av.y;
        As[lc + 2][lr] = av.z; As[lc + 3][lr] = av.w;
        Bs[lc + 0][lr] = bv.x; Bs[lc + 1][lr] = bv.y;
        Bs[lc + 2][lr] = bv.z; Bs[lc + 3][lr] = bv.w;
        __syncthreads();
#pragma unroll
        for (int kk = 0; kk < 8; kk++) {
            float a[8], b[8];
            *(float4*)&a[0] = *(const float4*)&As[kk][ty * 8];
            *(float4*)&a[4] = *(const float4*)&As[kk][ty * 8 + 4];
            *(float4*)&b[0] = *(const float4*)&Bs[kk][tx * 8];
            *(float4*)&b[4] = *(const float4*)&Bs[kk][tx * 8 + 4];
#pragma unroll
            for (int i = 0; i < 8; i++)
#pragma unroll
                for (int j = 0; j < 8; j++)
                    acc[i][j] += a[i] * b[j];
        }
        __syncthreads();
    }

#pragma unroll
    for (int i = 0; i < 8; i++) {
        const int row = bm + ty * 8 + i;
        const int col = bn + tx * 8;
        float v[8];
#pragma unroll
        for (int j = 0; j < 8; j++) v[j] = acc[i][j] + bias[col + j];
        if (flags & 2) {
#pragma unroll
            for (int j = 0; j < 8; j++) v[j] = gelu_exact(v[j]);
        }
        if (flags & 1) {
            const float* R = Cres + (size_t)row * N + col;
#pragma unroll
            for (int j = 0; j < 8; j++) v[j] += R[j];
        }
        float* Crow = C + (size_t)row * N + col;
        *(float4*)Crow       = make_float4(v[0], v[1], v[2], v[3]);
        *(float4*)(Crow + 4) = make_float4(v[4], v[5], v[6], v[7]);
    }
}

// ---------------- LayerNorm (two-pass), one block per row ------------------
__global__ void __launch_bounds__(256) ln_kernel(
    const float* __restrict__ x, const float* __restrict__ s,
    const float* __restrict__ b, float* __restrict__ y, int W)
{
    __shared__ float red[9];
    const int row = blockIdx.x;
    const int tid = threadIdx.x;
    const float* xr = x + (size_t)row * W;

    float sum = 0.f;
    for (int i = tid; i < W; i += 256) sum += xr[i];
#pragma unroll
    for (int o = 16; o > 0; o >>= 1) sum += __shfl_xor_sync(~0u, sum, o);
    if ((tid & 31) == 0) red[tid >> 5] = sum;
    __syncthreads();
    if (tid == 0) {
        float t = 0.f;
        for (int w = 0; w < 8; w++) t += red[w];
        red[8] = t;
    }
    __syncthreads();
    const float mu = red[8] / (float)W;

    float var = 0.f;
    for (int i = tid; i < W; i += 256) { float d = xr[i] - mu; var += d * d; }
    __syncthreads();   // everyone has read red[8] before reuse
#pragma unroll
    for (int o = 16; o > 0; o >>= 1) var += __shfl_xor_sync(~0u, var, o);
    if ((tid & 31) == 0) red[tid >> 5] = var;
    __syncthreads();
    if (tid == 0) {
        float t = 0.f;
        for (int w = 0; w < 8; w++) t += red[w];
        red[8] = t;
    }
    __syncthreads();
    const float inv = rsqrtf(red[8] / (float)W + 1e-6f);

    float* yr = y + (size_t)row * W;
    for (int i = tid; i < W; i += 256)
        yr[i] = (xr[i] - mu) * inv * s[i] + b[i];
}

// ---------------- RoPE table init (merge-order positions) ------------------
__global__ void init_rope(float* __restrict__ cosT, float* __restrict__ sinT)
{
    int idx = blockIdx.x * blockDim.x + threadIdx.x;   // SEQ*64
    if (idx >= SEQ * HD) return;
    int t = idx >> 6, d = idx & 63;
    int bh = t >> 6, r = t & 63, bw = r >> 2, ih = (r >> 1) & 1, iw = r & 1;
    float hp = (float)(bh * 2 + ih);
    float wp = (float)(bw * 2 + iw);
    int base = d & 31;
    float pos, inv;
    if (base < 16) { pos = hp; inv = powf(10000.f, -(float)base / 16.f); }
    else           { pos = wp; inv = powf(10000.f, -(float)(base - 16) / 16.f); }
    float ang = pos * inv;
    cosT[idx] = cosf(ang);
    sinT[idx] = sinf(ang);
}

// ---------------- positional embedding add ---------------------------------
__global__ void add_pos(float* __restrict__ x, const float* __restrict__ pos_table)
{
    int idx = blockIdx.x * blockDim.x + threadIdx.x;   // SEQ*DIM
    int t = idx >> 10, c = idx & 1023;
    int bh = t >> 6, r = t & 63, bw = r >> 2, ih = (r >> 1) & 1, iw = r & 1;
    int pid = (bh * 2 + ih) * 48 + (bw * 2 + iw);
    x[idx] += pos_table[(size_t)pid * DIM + c];
}

// ---------------- RoPE + repack: qkv -> q_r/k_r/v_r [H,S,64] ---------------
__global__ void rope_repack(
    const float* __restrict__ qkv, const float* __restrict__ cosT,
    const float* __restrict__ sinT, float* __restrict__ qr,
    float* __restrict__ kr, float* __restrict__ vr)
{
    int idx = blockIdx.x * blockDim.x + threadIdx.x;   // SEQ*NHEAD*32
    if (idx >= SEQ * NHEAD * 32) return;
    int d = idx & 31;
    int h = (idx >> 5) & 15;
    int t = idx >> 9;

    const float* base = qkv + (size_t)t * 3072 + h * 64;
    float c1 = cosT[t * 64 + d],      s1 = sinT[t * 64 + d];
    float c2 = cosT[t * 64 + d + 32], s2 = sinT[t * 64 + d + 32];
    size_t o = ((size_t)(h << 10) + t) * 64;

    float x1 = base[d], x2 = base[d + 32];
    qr[o + d]      = x1 * c1 - x2 * s1;
    qr[o + d + 32] = x2 * c2 + x1 * s2;

    const float* kb = base + 1024;
    x1 = kb[d]; x2 = kb[d + 32];
    kr[o + d]      = x1 * c1 - x2 * s1;
    kr[o + d + 32] = x2 * c2 + x1 * s2;

    const float* vb = base + 2048;
    vr[o + d]      = vb[d];
    vr[o + d + 32] = vb[d + 32];
}

// ---------------- fused attention: one block per (q, head) -----------------
__global__ void __launch_bounds__(128) attn_kernel(
    const float* __restrict__ qr, const float* __restrict__ kr,
    const float* __restrict__ vr, float* __restrict__ outp)
{
    __shared__ float s[1024];
    __shared__ float tile[128][65];
    __shared__ float qv[64];
    __shared__ float red[4];
    __shared__ float bc[2];
    const int q = blockIdx.x, h = blockIdx.y, tid = threadIdx.x;

    if (tid < 64) qv[tid] = qr[((size_t)(h << 10) + q) * 64 + tid];
    __syncthreads();

    // scores
    for (int kt = 0; kt < 1024; kt += 128) {
        const float* kb = kr + ((size_t)(h << 10) + kt) * 64;
        for (int i = tid; i < 128 * 64; i += 128) tile[i >> 6][i & 63] = kb[i];
        __syncthreads();
        float acc = 0.f;
#pragma unroll
        for (int d = 0; d < 64; d++) acc += qv[d] * tile[tid][d];
        s[kt + tid] = acc * 0.125f;   // HD^-0.5
        __syncthreads();
    }

    // softmax
    float m = -1e30f;
    for (int i = tid; i < 1024; i += 128) m = fmaxf(m, s[i]);
#pragma unroll
    for (int o = 16; o > 0; o >>= 1) m = fmaxf(m, __shfl_xor_sync(~0u, m, o));
    if ((tid & 31) == 0) red[tid >> 5] = m;
    __syncthreads();
    if (tid == 0) {
        float t = red[0];
        for (int w = 1; w < 4; w++) t = fmaxf(t, red[w]);
        bc[0] = t;
    }
    __syncthreads();
    const float M = bc[0];
    float sum = 0.f;
    for (int i = tid; i < 1024; i += 128) {
        float e = __expf(s[i] - M);
        s[i] = e;
        sum += e;
    }
#pragma unroll
    for (int o = 16; o > 0; o >>= 1) sum += __shfl_xor_sync(~0u, sum, o);
    if ((tid & 31) == 0) red[tid >> 5] = sum;
    __syncthreads();
    if (tid == 0) {
        float t = 0.f;
        for (int w = 0; w < 4; w++) t += red[w];
        bc[1] = 1.0f / t;
    }
    __syncthreads();
    const float invS = bc[1];

    // P @ V
    const int d = tid & 63, half = tid >> 6;
    float acc = 0.f;
    for (int kt = 0; kt < 1024; kt += 128) {
        const float* vb = vr + ((size_t)(h << 10) + kt) * 64;
        for (int i = tid; i < 128 * 64; i += 128) tile[i >> 6][i & 63] = vb[i];
        __syncthreads();
        const int k0 = half << 6;
#pragma unroll
        for (int kk = 0; kk < 64; kk++)
            acc += s[kt + k0 + kk] * tile[k0 + kk][d];
        __syncthreads();
    }
    s[tid] = acc;
    __syncthreads();
    if (tid < 64)
        outp[(size_t)q * DIM + (h << 6) + tid] = (s[tid] + s[tid + 64]) * invS;
}

// ---------------- copy ------------------------------------------------------
__global__ void copy_kernel(float* __restrict__ dst, const float* __restrict__ src, int n)
{
    int i = blockIdx.x * blockDim.x + threadIdx.x;
    if (i < n) dst[i] = src[i];
}

// ---------------- launch ----------------------------------------------------
extern "C" void kernel_launch(void* const* d_in, const int* in_sizes, int n_in,
                              void* d_out, int out_size)
{
    (void)in_sizes; (void)n_in; (void)out_size;
    const float* pixel     = (const float*)d_in[0];
    const float* conv_w    = (const float*)d_in[1];
    const float* conv_b    = (const float*)d_in[2];
    const float* pos_table = (const float*)d_in[3];
    const float* ln1_s     = (const float*)d_in[4];
    const float* ln1_b     = (const float*)d_in[5];
    const float* ln2_s     = (const float*)d_in[6];
    const float* ln2_b     = (const float*)d_in[7];
    const float* qkv_w     = (const float*)d_in[8];
    const float* qkv_b     = (const float*)d_in[9];
    const float* proj_w    = (const float*)d_in[10];
    const float* proj_b    = (const float*)d_in[11];
    const float* fc1_w     = (const float*)d_in[12];
    const float* fc1_b     = (const float*)d_in[13];
    const float* fc2_w     = (const float*)d_in[14];
    const float* fc2_b     = (const float*)d_in[15];
    const float* mrg_ln_s  = (const float*)d_in[16];
    const float* mrg_ln_b  = (const float*)d_in[17];
    const float* mrg_fc1_w = (const float*)d_in[18];
    const float* mrg_fc1_b = (const float*)d_in[19];
    const float* mrg_fc2_w = (const float*)d_in[20];
    const float* mrg_fc2_b = (const float*)d_in[21];
    const float* ds_ln_s   = (const float*)d_in[22];
    const float* ds_ln_b   = (const float*)d_in[23];
    const float* ds_fc1_w  = (const float*)d_in[24];
    const float* ds_fc1_b  = (const float*)d_in[25];
    const float* ds_fc2_w  = (const float*)d_in[26];
    const float* ds_fc2_b  = (const float*)d_in[27];
    float* out = (float*)d_out;

    float *x, *h, *qkv, *qr, *kr, *vr, *attn, *ff, *ds, *cosT, *sinT;
    cudaGetSymbolAddress((void**)&x,    g_x);
    cudaGetSymbolAddress((void**)&h,    g_h);
    cudaGetSymbolAddress((void**)&qkv,  g_qkv);
    cudaGetSymbolAddress((void**)&qr,   g_qr);
    cudaGetSymbolAddress((void**)&kr,   g_kr);
    cudaGetSymbolAddress((void**)&vr,   g_vr);
    cudaGetSymbolAddress((void**)&attn, g_attn);
    cudaGetSymbolAddress((void**)&ff,   g_ff);
    cudaGetSymbolAddress((void**)&ds,   g_ds);
    cudaGetSymbolAddress((void**)&cosT, g_cos);
    cudaGetSymbolAddress((void**)&sinT, g_sin);

    init_rope<<<(SEQ * HD + 255) / 256, 256>>>(cosT, sinT);

    // patch embed + pos
    gemm_nt<<<dim3(DIM / 128, SEQ / 128), 256>>>(pixel, conv_w, conv_b, nullptr,
                                                 x, SEQ, DIM, 1536, 0);
    add_pos<<<(SEQ * DIM) / 256, 256>>>(x, pos_table);

    for (int i = 0; i < DEPTH; i++) {
        ln_kernel<<<SEQ, 256>>>(x, ln1_s + i * DIM, ln1_b + i * DIM, h, DIM);
        gemm_nt<<<dim3(3 * DIM / 128, SEQ / 128), 256>>>(
            h, qkv_w + (size_t)i * 3 * DIM * DIM, qkv_b + (size_t)i * 3 * DIM,
            nullptr, qkv, SEQ, 3 * DIM, DIM, 0);
        rope_repack<<<(SEQ * NHEAD * 32) / 256, 256>>>(qkv, cosT, sinT, qr, kr, vr);
        attn_kernel<<<dim3(SEQ, NHEAD), 128>>>(qr, kr, vr, attn);
        gemm_nt<<<dim3(DIM / 128, SEQ / 128), 256>>>(
            attn, proj_w + (size_t)i * DIM * DIM, proj_b + (size_t)i * DIM,
            x, x, SEQ, DIM, DIM, 1);
        ln_kernel<<<SEQ, 256>>>(x, ln2_s + i * DIM, ln2_b + i * DIM, h, DIM);
        gemm_nt<<<dim3(FFD / 128, SEQ / 128), 256>>>(
            h, fc1_w + (size_t)i * FFD * DIM, fc1_b + (size_t)i * FFD,
            nullptr, ff, SEQ, FFD, DIM, 2);
        gemm_nt<<<dim3(DIM / 128, SEQ / 128), 256>>>(
            ff, fc2_w + (size_t)i * DIM * FFD, fc2_b + (size_t)i * DIM,
            x, x, SEQ, DIM, FFD, 1);
        if (i == 5)  copy_kernel<<<(SEQ * DIM) / 256, 256>>>(ds,                x, SEQ * DIM);
        if (i == 11) copy_kernel<<<(SEQ * DIM) / 256, 256>>>(ds + SEQ * DIM,     x, SEQ * DIM);
        if (i == 17) copy_kernel<<<(SEQ * DIM) / 256, 256>>>(ds + 2 * SEQ * DIM, x, SEQ * DIM);
    }

    // output 0: final hidden states
    copy_kernel<<<(SEQ * DIM) / 256, 256>>>(out, x, SEQ * DIM);

    // pooled merger (pre-shuffle LN over D=1024)
    ln_kernel<<<SEQ, 256>>>(x, mrg_ln_s, mrg_ln_b, h, DIM);
    gemm_nt<<<dim3(4096 / 128, 256 / 128), 256>>>(h, mrg_fc1_w, mrg_fc1_b,
                                                  nullptr, ff, 256, 4096, 4096, 2);
    gemm_nt<<<dim3(OUTD / 128, 256 / 128), 256>>>(ff, mrg_fc2_w, mrg_fc2_b,
                                                  nullptr, out + SEQ * DIM,
                                                  256, OUTD, 4096, 0);

    // deepstack mergers (post-shuffle LN over 4096)
    for (int j = 0; j < 3; j++) {
        ln_kernel<<<256, 256>>>(ds + (size_t)j * SEQ * DIM,
                                ds_ln_s + j * 4096, ds_ln_b + j * 4096, h, 4096);
        gemm_nt<<<dim3(4096 / 128, 256 / 128), 256>>>(
            h, ds_fc1_w + (size_t)j * 4096 * 4096, ds_fc1_b + (size_t)j * 4096,
            nullptr, ff, 256, 4096, 4096, 2);
        gemm_nt<<<dim3(OUTD / 128, 256 / 128), 256>>>(
            ff, ds_fc2_w + (size_t)j * OUTD * 4096, ds_fc2_b + (size_t)j * OUTD,
            nullptr, out + SEQ * DIM + (size_t)(j + 1) * 256 * OUTD,
            256, OUTD, 4096, 0);
    }
}

// round 3
// speedup vs baseline: 3.6830x; 3.6830x over previous
#include <cuda_runtime.h>
#include <cuda_bf16.h>
#include <math.h>
#include <stdint.h>

#define SEQ   1024
#define DIM   1024
#define NHEAD 16
#define HD    64
#define FFD   4096
#define DEPTH 24
#define OUTD  2560

// ---------------- scratch (device globals; no allocations) ----------------
__device__ float g_x   [SEQ*DIM];
__device__ float g_h   [SEQ*DIM];      // ln output; also viewed as [256,4096]
__device__ float g_qkv [SEQ*3*DIM];
__device__ float g_qr  [NHEAD*SEQ*HD];
__device__ float g_kr  [NHEAD*SEQ*HD];
__device__ float g_vr  [NHEAD*SEQ*HD];
__device__ float g_attn[SEQ*DIM];
__device__ float g_ff  [SEQ*FFD];      // also merger hidden [256,4096]
__device__ float g_ds  [3*SEQ*DIM];
__device__ float g_cos [SEQ*HD];
__device__ float g_sin [SEQ*HD];

__device__ __forceinline__ float gelu_exact(float x) {
    return 0.5f * x * (1.0f + erff(x * 0.70710678118654752f));
}

// split fp32 -> bf16 hi + bf16 lo, packed as bf16x2 pairs (low half = first elem)
__device__ __forceinline__ void split2(float x, float y, uint32_t& hi, uint32_t& lo) {
    __nv_bfloat16 xh = __float2bfloat16(x);
    __nv_bfloat16 yh = __float2bfloat16(y);
    __nv_bfloat16 xl = __float2bfloat16(x - __bfloat162float(xh));
    __nv_bfloat16 yl = __float2bfloat16(y - __bfloat162float(yh));
    __nv_bfloat162 h2 = __halves2bfloat162(xh, yh);
    __nv_bfloat162 l2 = __halves2bfloat162(xl, yl);
    hi = *(uint32_t*)&h2;
    lo = *(uint32_t*)&l2;
}

#define MMA_BF16(d, a, b0, b1)                                                 \
    asm volatile("mma.sync.aligned.m16n8k16.row.col.f32.bf16.bf16.f32 "        \
                 "{%0,%1,%2,%3},{%4,%5,%6,%7},{%8,%9},{%0,%1,%2,%3};"          \
                 : "+f"(d[0]), "+f"(d[1]), "+f"(d[2]), "+f"(d[3])              \
                 : "r"(a[0]), "r"(a[1]), "r"(a[2]), "r"(a[3]), "r"(b0), "r"(b1))

// ---------------- tensor-core GEMM: C = op(A[M,K] @ B[N,K]^T + bias) -------
// split-bf16 x3 passes for ~fp32 accuracy. flags: bit0 residual, bit1 gelu.
// M%128==0, N%128==0, K%32==0.
__global__ void __launch_bounds__(256) gemm_bf16x3(
    const float* __restrict__ A, const float* __restrict__ B,
    const float* __restrict__ bias, const float* __restrict__ Cres,
    float* __restrict__ C, int M, int N, int K, int flags)
{
    __shared__ uint32_t sAh[128*17], sAl[128*17], sBh[128*17], sBl[128*17];
    const int bm = blockIdx.y * 128, bn = blockIdx.x * 128;
    const int tid = threadIdx.x;
    const int wid = tid >> 5, lane = tid & 31;
    const int wm = wid >> 1, wn = wid & 1;            // 4x2 warp grid
    const int lrow = tid >> 3, lc4 = tid & 7;          // loader: row, float4-col

    float acc[2][8][4];
#pragma unroll
    for (int i = 0; i < 2; i++)
#pragma unroll
        for (int j = 0; j < 8; j++)
#pragma unroll
            for (int c = 0; c < 4; c++) acc[i][j][c] = 0.f;

    const float* Ap = A + (size_t)(bm + lrow) * K + lc4 * 4;
    const float* Bp = B + (size_t)(bn + lrow) * K + lc4 * 4;

    // prefetch tile 0 into registers: 4 rows (stride 32) each of A and B
    float4 ra[4], rb[4];
#pragma unroll
    for (int r = 0; r < 4; r++) {
        ra[r] = *(const float4*)(Ap + (size_t)(r * 32) * K);
        rb[r] = *(const float4*)(Bp + (size_t)(r * 32) * K);
    }

    for (int k0 = 0; k0 < K; k0 += 32) {
        // store staged tile to smem (with split conversion) — full 128 rows
#pragma unroll
        for (int r = 0; r < 4; r++) {
            uint32_t h0, l0, h1, l1;
            int base = (lrow + r * 32) * 17 + lc4 * 2;
            split2(ra[r].x, ra[r].y, h0, l0); split2(ra[r].z, ra[r].w, h1, l1);
            sAh[base] = h0; sAl[base] = l0; sAh[base + 1] = h1; sAl[base + 1] = l1;
            split2(rb[r].x, rb[r].y, h0, l0); split2(rb[r].z, rb[r].w, h1, l1);
            sBh[base] = h0; sBl[base] = l0; sBh[base + 1] = h1; sBl[base + 1] = l1;
        }
        __syncthreads();

        // prefetch next tile
        if (k0 + 32 < K) {
            const float* Apn = Ap + k0 + 32;
            const float* Bpn = Bp + k0 + 32;
#pragma unroll
            for (int r = 0; r < 4; r++) {
                ra[r] = *(const float4*)(Apn + (size_t)(r * 32) * K);
                rb[r] = *(const float4*)(Bpn + (size_t)(r * 32) * K);
            }
        }

#pragma unroll
        for (int ks = 0; ks < 2; ks++) {
            uint32_t ah[2][4], al[2][4];
            const int kp = ks * 8 + (lane & 3);
#pragma unroll
            for (int i = 0; i < 2; i++) {
                int r0 = wm * 32 + i * 16 + (lane >> 2);
                ah[i][0] = sAh[r0 * 17 + kp];
                ah[i][1] = sAh[(r0 + 8) * 17 + kp];
                ah[i][2] = sAh[r0 * 17 + kp + 4];
                ah[i][3] = sAh[(r0 + 8) * 17 + kp + 4];
                al[i][0] = sAl[r0 * 17 + kp];
                al[i][1] = sAl[(r0 + 8) * 17 + kp];
                al[i][2] = sAl[r0 * 17 + kp + 4];
                al[i][3] = sAl[(r0 + 8) * 17 + kp + 4];
            }
#pragma unroll
            for (int j = 0; j < 8; j++) {
                int n = wn * 64 + j * 8 + (lane >> 2);
                uint32_t bh0 = sBh[n * 17 + kp], bh1 = sBh[n * 17 + kp + 4];
                uint32_t bl0 = sBl[n * 17 + kp], bl1 = sBl[n * 17 + kp + 4];
#pragma unroll
                for (int i = 0; i < 2; i++) {
                    MMA_BF16(acc[i][j], ah[i], bh0, bh1);
                    MMA_BF16(acc[i][j], ah[i], bl0, bl1);
                    MMA_BF16(acc[i][j], al[i], bh0, bh1);
                }
            }
        }
        __syncthreads();
    }

    // epilogue
#pragma unroll
    for (int i = 0; i < 2; i++) {
        int r0 = bm + wm * 32 + i * 16 + (lane >> 2);
#pragma unroll
        for (int j = 0; j < 8; j++) {
            int col = bn + wn * 64 + j * 8 + (lane & 3) * 2;
            float b0 = bias[col], b1 = bias[col + 1];
#pragma unroll
            for (int half = 0; half < 2; half++) {
                int row = r0 + half * 8;
                float v0 = acc[i][j][half * 2 + 0] + b0;
                float v1 = acc[i][j][half * 2 + 1] + b1;
                if (flags & 2) { v0 = gelu_exact(v0); v1 = gelu_exact(v1); }
                if (flags & 1) {
                    const float* R = Cres + (size_t)row * N + col;
                    v0 += R[0]; v1 += R[1];
                }
                *(float2*)(C + (size_t)row * N + col) = make_float2(v0, v1);
            }
        }
    }
}

// ---------------- LayerNorm (two-pass), one block per row ------------------
__global__ void __launch_bounds__(256) ln_kernel(
    const float* __restrict__ x, const float* __restrict__ s,
    const float* __restrict__ b, float* __restrict__ y, int W)
{
    __shared__ float red[9];
    const int row = blockIdx.x;
    const int tid = threadIdx.x;
    const float* xr = x + (size_t)row * W;

    float sum = 0.f;
    for (int i = tid; i < W; i += 256) sum += xr[i];
#pragma unroll
    for (int o = 16; o > 0; o >>= 1) sum += __shfl_xor_sync(~0u, sum, o);
    if ((tid & 31) == 0) red[tid >> 5] = sum;
    __syncthreads();
    if (tid == 0) {
        float t = 0.f;
        for (int w = 0; w < 8; w++) t += red[w];
        red[8] = t;
    }
    __syncthreads();
    const float mu = red[8] / (float)W;

    float var = 0.f;
    for (int i = tid; i < W; i += 256) { float d = xr[i] - mu; var += d * d; }
    __syncthreads();
#pragma unroll
    for (int o = 16; o > 0; o >>= 1) var += __shfl_xor_sync(~0u, var, o);
    if ((tid & 31) == 0) red[tid >> 5] = var;
    __syncthreads();
    if (tid == 0) {
        float t = 0.f;
        for (int w = 0; w < 8; w++) t += red[w];
        red[8] = t;
    }
    __syncthreads();
    const float inv = rsqrtf(red[8] / (float)W + 1e-6f);

    float* yr = y + (size_t)row * W;
    for (int i = tid; i < W; i += 256)
        yr[i] = (xr[i] - mu) * inv * s[i] + b[i];
}

// ---------------- RoPE table init (merge-order positions) ------------------
__global__ void init_rope(float* __restrict__ cosT, float* __restrict__ sinT)
{
    int idx = blockIdx.x * blockDim.x + threadIdx.x;   // SEQ*64
    if (idx >= SEQ * HD) return;
    int t = idx >> 6, d = idx & 63;
    int bh = t >> 6, r = t & 63, bw = r >> 2, ih = (r >> 1) & 1, iw = r & 1;
    float hp = (float)(bh * 2 + ih);
    float wp = (float)(bw * 2 + iw);
    int base = d & 31;
    float pos, inv;
    if (base < 16) { pos = hp; inv = powf(10000.f, -(float)base / 16.f); }
    else           { pos = wp; inv = powf(10000.f, -(float)(base - 16) / 16.f); }
    float ang = pos * inv;
    cosT[idx] = cosf(ang);
    sinT[idx] = sinf(ang);
}

// ---------------- positional embedding add ---------------------------------
__global__ void add_pos(float* __restrict__ x, const float* __restrict__ pos_table)
{
    int idx = blockIdx.x * blockDim.x + threadIdx.x;   // SEQ*DIM
    int t = idx >> 10, c = idx & 1023;
    int bh = t >> 6, r = t & 63, bw = r >> 2, ih = (r >> 1) & 1, iw = r & 1;
    int pid = (bh * 2 + ih) * 48 + (bw * 2 + iw);
    x[idx] += pos_table[(size_t)pid * DIM + c];
}

// ---------------- RoPE + repack: qkv -> q_r/k_r/v_r [H,S,64] ---------------
__global__ void rope_repack(
    const float* __restrict__ qkv, const float* __restrict__ cosT,
    const float* __restrict__ sinT, float* __restrict__ qr,
    float* __restrict__ kr, float* __restrict__ vr)
{
    int idx = blockIdx.x * blockDim.x + threadIdx.x;   // SEQ*NHEAD*32
    if (idx >= SEQ * NHEAD * 32) return;
    int d = idx & 31;
    int h = (idx >> 5) & 15;
    int t = idx >> 9;

    const float* base = qkv + (size_t)t * 3072 + h * 64;
    float c1 = cosT[t * 64 + d],      s1 = sinT[t * 64 + d];
    float c2 = cosT[t * 64 + d + 32], s2 = sinT[t * 64 + d + 32];
    size_t o = ((size_t)(h << 10) + t) * 64;

    float x1 = base[d], x2 = base[d + 32];
    qr[o + d]      = x1 * c1 - x2 * s1;
    qr[o + d + 32] = x2 * c2 + x1 * s2;

    const float* kb = base + 1024;
    x1 = kb[d]; x2 = kb[d + 32];
    kr[o + d]      = x1 * c1 - x2 * s1;
    kr[o + d + 32] = x2 * c2 + x1 * s2;

    const float* vb = base + 2048;
    vr[o + d]      = vb[d];
    vr[o + d + 32] = vb[d + 32];
}

// ---------------- flash attention: 128 queries per block, fp32 -------------
// grid (SEQ/128, NHEAD), 256 threads. thread t: qb=t/8 (4 q rows), kb=t%8
// (8-wide k block in S phase / d block in PV phase).
#define ATTN_SMEM ((128*65 + 64*65 + 64*65 + 128*65) * 4)
__global__ void __launch_bounds__(256) attn_flash(
    const float* __restrict__ qr, const float* __restrict__ kr,
    const float* __restrict__ vr, float* __restrict__ outp)
{
    extern __shared__ float sm[];
    float* Qs = sm;                  // [128][65]
    float* Ks = Qs + 128 * 65;       // [64][65]
    float* Vs = Ks + 64 * 65;        // [64][65]
    float* Ss = Vs + 64 * 65;        // [128][65]

    const int h = blockIdx.y, qt = blockIdx.x;
    const int tid = threadIdx.x;
    const int qb = tid >> 3;         // 0..31
    const int kb = tid & 7;          // 0..7

    const float* Qg = qr + ((size_t)(h << 10) + qt * 128) * 64;
    for (int i = tid; i < 128 * 64; i += 256)
        Qs[(i >> 6) * 65 + (i & 63)] = Qg[i] * 0.125f;  // fold HD^-0.5

    float m[4], l[4], O[4][8];
#pragma unroll
    for (int q = 0; q < 4; q++) {
        m[q] = -1e30f; l[q] = 0.f;
#pragma unroll
        for (int d = 0; d < 8; d++) O[q][d] = 0.f;
    }

    for (int kt = 0; kt < 1024; kt += 64) {
        __syncthreads();
        const float* Kg = kr + ((size_t)(h << 10) + kt) * 64;
        const float* Vg = vr + ((size_t)(h << 10) + kt) * 64;
        for (int i = tid; i < 64 * 64; i += 256) {
            int r = i >> 6, c = i & 63;
            Ks[r * 65 + c] = Kg[i];
            Vs[r * 65 + c] = Vg[i];
        }
        __syncthreads();

        // S = Q K^T (4 q x 8 k per thread)
        float s[4][8];
#pragma unroll
        for (int q = 0; q < 4; q++)
#pragma unroll
            for (int k = 0; k < 8; k++) s[q][k] = 0.f;

        for (int d = 0; d < 64; d++) {
            float qv[4], kv[8];
#pragma unroll
            for (int q = 0; q < 4; q++) qv[q] = Qs[(qb * 4 + q) * 65 + d];
#pragma unroll
            for (int k = 0; k < 8; k++) kv[k] = Ks[(kb * 8 + k) * 65 + d];
#pragma unroll
            for (int q = 0; q < 4; q++)
#pragma unroll
                for (int k = 0; k < 8; k++) s[q][k] += qv[q] * kv[k];
        }

        // online softmax update
#pragma unroll
        for (int q = 0; q < 4; q++) {
            float mt = s[q][0];
#pragma unroll
            for (int k = 1; k < 8; k++) mt = fmaxf(mt, s[q][k]);
            mt = fmaxf(mt, __shfl_xor_sync(~0u, mt, 1));
            mt = fmaxf(mt, __shfl_xor_sync(~0u, mt, 2));
            mt = fmaxf(mt, __shfl_xor_sync(~0u, mt, 4));
            float mnew = fmaxf(m[q], mt);
            float scale = __expf(m[q] - mnew);
            float ls = 0.f;
#pragma unroll
            for (int k = 0; k < 8; k++) {
                float p = __expf(s[q][k] - mnew);
                Ss[(qb * 4 + q) * 65 + kb * 8 + k] = p;
                ls += p;
            }
            ls += __shfl_xor_sync(~0u, ls, 1);
            ls += __shfl_xor_sync(~0u, ls, 2);
            ls += __shfl_xor_sync(~0u, ls, 4);
            l[q] = l[q] * scale + ls;
            m[q] = mnew;
#pragma unroll
            for (int d = 0; d < 8; d++) O[q][d] *= scale;
        }
        __syncwarp();

        // O += P V  (d block = kb*8..+7)
        for (int k = 0; k < 64; k++) {
            float vv[8];
#pragma unroll
            for (int d = 0; d < 8; d++) vv[d] = Vs[k * 65 + kb * 8 + d];
#pragma unroll
            for (int q = 0; q < 4; q++) {
                float p = Ss[(qb * 4 + q) * 65 + k];
#pragma unroll
                for (int d = 0; d < 8; d++) O[q][d] += p * vv[d];
            }
        }
    }

#pragma unroll
    for (int q = 0; q < 4; q++) {
        float inv = 1.0f / l[q];
        int qg = qt * 128 + qb * 4 + q;
#pragma unroll
        for (int d = 0; d < 8; d++)
            outp[(size_t)qg * DIM + (h << 6) + kb * 8 + d] = O[q][d] * inv;
    }
}

// ---------------- copy ------------------------------------------------------
__global__ void copy_kernel(float* __restrict__ dst, const float* __restrict__ src, int n)
{
    int i = blockIdx.x * blockDim.x + threadIdx.x;
    if (i < n) dst[i] = src[i];
}

// ---------------- launch ----------------------------------------------------
extern "C" void kernel_launch(void* const* d_in, const int* in_sizes, int n_in,
                              void* d_out, int out_size)
{
    (void)in_sizes; (void)n_in; (void)out_size;
    const float* pixel     = (const float*)d_in[0];
    const float* conv_w    = (const float*)d_in[1];
    const float* conv_b    = (const float*)d_in[2];
    const float* pos_table = (const float*)d_in[3];
    const float* ln1_s     = (const float*)d_in[4];
    const float* ln1_b     = (const float*)d_in[5];
    const float* ln2_s     = (const float*)d_in[6];
    const float* ln2_b     = (const float*)d_in[7];
    const float* qkv_w     = (const float*)d_in[8];
    const float* qkv_b     = (const float*)d_in[9];
    const float* proj_w    = (const float*)d_in[10];
    const float* proj_b    = (const float*)d_in[11];
    const float* fc1_w     = (const float*)d_in[12];
    const float* fc1_b     = (const float*)d_in[13];
    const float* fc2_w     = (const float*)d_in[14];
    const float* fc2_b     = (const float*)d_in[15];
    const float* mrg_ln_s  = (const float*)d_in[16];
    const float* mrg_ln_b  = (const float*)d_in[17];
    const float* mrg_fc1_w = (const float*)d_in[18];
    const float* mrg_fc1_b = (const float*)d_in[19];
    const float* mrg_fc2_w = (const float*)d_in[20];
    const float* mrg_fc2_b = (const float*)d_in[21];
    const float* ds_ln_s   = (const float*)d_in[22];
    const float* ds_ln_b   = (const float*)d_in[23];
    const float* ds_fc1_w  = (const float*)d_in[24];
    const float* ds_fc1_b  = (const float*)d_in[25];
    const float* ds_fc2_w  = (const float*)d_in[26];
    const float* ds_fc2_b  = (const float*)d_in[27];
    float* out = (float*)d_out;

    float *x, *h, *qkv, *qr, *kr, *vr, *attn, *ff, *ds, *cosT, *sinT;
    cudaGetSymbolAddress((void**)&x,    g_x);
    cudaGetSymbolAddress((void**)&h,    g_h);
    cudaGetSymbolAddress((void**)&qkv,  g_qkv);
    cudaGetSymbolAddress((void**)&qr,   g_qr);
    cudaGetSymbolAddress((void**)&kr,   g_kr);
    cudaGetSymbolAddress((void**)&vr,   g_vr);
    cudaGetSymbolAddress((void**)&attn, g_attn);
    cudaGetSymbolAddress((void**)&ff,   g_ff);
    cudaGetSymbolAddress((void**)&ds,   g_ds);
    cudaGetSymbolAddress((void**)&cosT, g_cos);
    cudaGetSymbolAddress((void**)&sinT, g_sin);

    cudaFuncSetAttribute(attn_flash,
                         cudaFuncAttributeMaxDynamicSharedMemorySize, ATTN_SMEM);

    init_rope<<<(SEQ * HD + 255) / 256, 256>>>(cosT, sinT);

    // patch embed + pos
    gemm_bf16x3<<<dim3(DIM / 128, SEQ / 128), 256>>>(pixel, conv_w, conv_b, nullptr,
                                                     x, SEQ, DIM, 1536, 0);
    add_pos<<<(SEQ * DIM) / 256, 256>>>(x, pos_table);

    for (int i = 0; i < DEPTH; i++) {
        ln_kernel<<<SEQ, 256>>>(x, ln1_s + i * DIM, ln1_b + i * DIM, h, DIM);
        gemm_bf16x3<<<dim3(3 * DIM / 128, SEQ / 128), 256>>>(
            h, qkv_w + (size_t)i * 3 * DIM * DIM, qkv_b + (size_t)i * 3 * DIM,
            nullptr, qkv, SEQ, 3 * DIM, DIM, 0);
        rope_repack<<<(SEQ * NHEAD * 32) / 256, 256>>>(qkv, cosT, sinT, qr, kr, vr);
        attn_flash<<<dim3(SEQ / 128, NHEAD), 256, ATTN_SMEM>>>(qr, kr, vr, attn);
        gemm_bf16x3<<<dim3(DIM / 128, SEQ / 128), 256>>>(
            attn, proj_w + (size_t)i * DIM * DIM, proj_b + (size_t)i * DIM,
            x, x, SEQ, DIM, DIM, 1);
        ln_kernel<<<SEQ, 256>>>(x, ln2_s + i * DIM, ln2_b + i * DIM, h, DIM);
        gemm_bf16x3<<<dim3(FFD / 128, SEQ / 128), 256>>>(
            h, fc1_w + (size_t)i * FFD * DIM, fc1_b + (size_t)i * FFD,
            nullptr, ff, SEQ, FFD, DIM, 2);
        gemm_bf16x3<<<dim3(DIM / 128, SEQ / 128), 256>>>(
            ff, fc2_w + (size_t)i * DIM * FFD, fc2_b + (size_t)i * DIM,
            x, x, SEQ, DIM, FFD, 1);
        if (i == 5)  copy_kernel<<<(SEQ * DIM) / 256, 256>>>(ds,                 x, SEQ * DIM);
        if (i == 11) copy_kernel<<<(SEQ * DIM) / 256, 256>>>(ds + SEQ * DIM,     x, SEQ * DIM);
        if (i == 17) copy_kernel<<<(SEQ * DIM) / 256, 256>>>(ds + 2 * SEQ * DIM, x, SEQ * DIM);
    }

    // output 0: final hidden states
    copy_kernel<<<(SEQ * DIM) / 256, 256>>>(out, x, SEQ * DIM);

    // pooled merger (pre-shuffle LN over D=1024)
    ln_kernel<<<SEQ, 256>>>(x, mrg_ln_s, mrg_ln_b, h, DIM);
    gemm_bf16x3<<<dim3(4096 / 128, 256 / 128), 256>>>(h, mrg_fc1_w, mrg_fc1_b,
                                                      nullptr, ff, 256, 4096, 4096, 2);
    gemm_bf16x3<<<dim3(OUTD / 128, 256 / 128), 256>>>(ff, mrg_fc2_w, mrg_fc2_b,
                                                      nullptr, out + SEQ * DIM,
                                                      256, OUTD, 4096, 0);

    // deepstack mergers (post-shuffle LN over 4096)
    for (int j = 0; j < 3; j++) {
        ln_kernel<<<256, 256>>>(ds + (size_t)j * SEQ * DIM,
                                ds_ln_s + j * 4096, ds_ln_b + j * 4096, h, 4096);
        gemm_bf16x3<<<dim3(4096 / 128, 256 / 128), 256>>>(
            h, ds_fc1_w + (size_t)j * 4096 * 4096, ds_fc1_b + (size_t)j * 4096,
            nullptr, ff, 256, 4096, 4096, 2);
        gemm_bf16x3<<<dim3(OUTD / 128, 256 / 128), 256>>>(
            ff, ds_fc2_w + (size_t)j * OUTD * 4096, ds_fc2_b + (size_t)j * OUTD,
            nullptr, out + SEQ * DIM + (size_t)(j + 1) * 256 * OUTD,
            256, OUTD, 4096, 0);
    }
}